// round 17
// baseline (speedup 1.0000x reference)
#include <cuda_runtime.h>

#define NSEG 256
#define D 128
#define OUT_ELEMS (NSEG * D)

#define BLOCKS 1184                        // 148 SMs x 8 CTAs, one full wave
#define THREADS 256
#define NWARPS (BLOCKS * (THREADS / 32))   // 9472
#define SLOTS_PER_WARP 4
#define TOT_SLOTS (NWARPS * SLOTS_PER_WARP)  // 37888 = 9472 merge-warps x 4

// ---------------------------------------------------------------------------
// Scratch (alloc-free rule: __device__ globals). Headers are fully rewritten
// by segsum every call (cnt=0 sentinels for unused slots) -> deterministic,
// no zeroing of the big scratch needed.
// ---------------------------------------------------------------------------
__device__ int    g_hseg[TOT_SLOTS];        // segment id per slot
__device__ int    g_hcnt[TOT_SLOTS];        // row count (0 = empty/sentinel)
__device__ float4 g_data[TOT_SLOTS][32];    // 128-float partial sum per slot
__device__ int    g_counts[NSEG];           // zeroed inline by segsum

// ---------------------------------------------------------------------------
// Pass 1: segmented sum (proven 81.4us R9 body, slot stores — no atomics).
// Also zeroes d_out and g_counts inline: segsum itself never reads or
// atomically writes d_out, so the kernel boundary orders it before merge.
// One warp owns a contiguous row chunk; lane l holds float4 cols [4l,4l+4).
// ---------------------------------------------------------------------------
__device__ __forceinline__ void write_slot(int slot, int lane, int seg_id,
                                           const float4& acc, int cnt) {
    g_data[slot][lane] = acc;
    if (lane == 0) {
        g_hseg[slot] = seg_id;
        g_hcnt[slot] = cnt;
    }
}

__global__ __launch_bounds__(THREADS, 8) void segsum_kernel(
    const float4* __restrict__ inp,   // (n, 32) float4 view of (n, 128) float
    const int* __restrict__ seg,      // (n,) sorted segment ids
    float* __restrict__ out,          // (256, 128): zeroed here for merge pass
    int n)
{
    // Inline zeroing duty (hidden under the 516MB stream).
    if (blockIdx.x < 32) {
        int i = blockIdx.x * THREADS + threadIdx.x;       // 8192 threads
        ((float4*)out)[i] = make_float4(0.f, 0.f, 0.f, 0.f);  // 8192 float4 = 128KB
        if (blockIdx.x == 0 && threadIdx.x < NSEG) g_counts[threadIdx.x] = 0;
    }

    const int lane = threadIdx.x & 31;
    const int warp_global = (blockIdx.x * blockDim.x + threadIdx.x) >> 5;

    const int rows_per_warp = (n + NWARPS - 1) / NWARPS;
    const int r0 = warp_global * rows_per_warp;
    const int r1 = min(n, r0 + rows_per_warp);
    const int slot0 = warp_global * SLOTS_PER_WARP;

    if (r0 >= r1) {
        // Empty tail warp: sentinel headers only (merge skips cnt==0).
        if (lane == 0) {
            #pragma unroll
            for (int k = 0; k < SLOTS_PER_WARP; ++k) g_hcnt[slot0 + k] = 0;
        }
        return;
    }

    int r = r0;
    const int first = seg[r0];
    const int last = seg[r1 - 1];

    float4 acc = make_float4(0.0f, 0.0f, 0.0f, 0.0f);
    int nslots = 0;

    if (first == last) {
        // -------- Uniform chunk (common case): streaming quad loop. ---------
        while (r + 4 <= r1) {
            float4 v0 = inp[(size_t)(r + 0) * 32 + lane];
            float4 v1 = inp[(size_t)(r + 1) * 32 + lane];
            float4 v2 = inp[(size_t)(r + 2) * 32 + lane];
            float4 v3 = inp[(size_t)(r + 3) * 32 + lane];
            acc.x += (v0.x + v1.x) + (v2.x + v3.x);
            acc.y += (v0.y + v1.y) + (v2.y + v3.y);
            acc.z += (v0.z + v1.z) + (v2.z + v3.z);
            acc.w += (v0.w + v1.w) + (v2.w + v3.w);
            r += 4;
        }
        for (; r < r1; ++r) {
            float4 v = inp[(size_t)r * 32 + lane];
            acc.x += v.x; acc.y += v.y; acc.z += v.z; acc.w += v.w;
        }
        write_slot(slot0, lane, first, acc, r1 - r0);
        nslots = 1;
    } else {
        // -------- Boundary chunk (rare, ~3% of warps). ----------------------
        int cnt = 0;
        int cur = first;
        while (r + 4 <= r1) {
            int s0 = seg[r];
            int s3 = seg[r + 3];
            float4 v0 = inp[(size_t)(r + 0) * 32 + lane];
            float4 v1 = inp[(size_t)(r + 1) * 32 + lane];
            float4 v2 = inp[(size_t)(r + 2) * 32 + lane];
            float4 v3 = inp[(size_t)(r + 3) * 32 + lane];
            if (s0 == cur && s3 == cur) {
                acc.x += (v0.x + v1.x) + (v2.x + v3.x);
                acc.y += (v0.y + v1.y) + (v2.y + v3.y);
                acc.z += (v0.z + v1.z) + (v2.z + v3.z);
                acc.w += (v0.w + v1.w) + (v2.w + v3.w);
                cnt += 4;
            } else {
                int s1 = seg[r + 1];
                int s2 = seg[r + 2];
                int   ss[4] = {s0, s1, s2, s3};
                float4 vv[4] = {v0, v1, v2, v3};
                #pragma unroll
                for (int i = 0; i < 4; ++i) {
                    if (ss[i] != cur) {
                        if (nslots < SLOTS_PER_WARP - 1) {
                            write_slot(slot0 + nslots, lane, cur, acc, cnt);
                            nslots++;
                        }
                        acc = make_float4(0.0f, 0.0f, 0.0f, 0.0f);
                        cnt = 0;
                        cur = ss[i];
                    }
                    acc.x += vv[i].x; acc.y += vv[i].y;
                    acc.z += vv[i].z; acc.w += vv[i].w;
                    cnt++;
                }
            }
            r += 4;
        }
        for (; r < r1; ++r) {
            int s = seg[r];
            float4 v = inp[(size_t)r * 32 + lane];
            if (s != cur) {
                if (nslots < SLOTS_PER_WARP - 1) {
                    write_slot(slot0 + nslots, lane, cur, acc, cnt);
                    nslots++;
                }
                acc = make_float4(0.0f, 0.0f, 0.0f, 0.0f);
                cnt = 0;
                cur = s;
            }
            acc.x += v.x; acc.y += v.y; acc.z += v.z; acc.w += v.w;
            cnt++;
        }
        write_slot(slot0 + nslots, lane, cur, acc, cnt);
        nslots++;
    }

    if (lane == 0) {
        for (int k = nslots; k < SLOTS_PER_WARP; ++k) g_hcnt[slot0 + k] = 0;
    }
}

// ---------------------------------------------------------------------------
// Pass 2: full-width slot merge. One warp per 4 slots (9472 warps = 37888
// slots exactly). Real slots (~9.7K) are atomically folded into d_out and
// g_counts; spread REDG across 32K addresses at 1184-CTA parallelism.
// ---------------------------------------------------------------------------
__global__ __launch_bounds__(THREADS) void merge_kernel(float* __restrict__ out) {
    const int lane = threadIdx.x & 31;
    const int w = (blockIdx.x * blockDim.x + threadIdx.x) >> 5;

    #pragma unroll
    for (int k = 0; k < SLOTS_PER_WARP; ++k) {
        int slot = w * SLOTS_PER_WARP + k;
        int cnt = g_hcnt[slot];          // uniform per warp -> L1 broadcast
        if (cnt > 0) {
            int s = g_hseg[slot];
            float4 v = g_data[slot][lane];
            float* p = out + s * D + lane * 4;
            atomicAdd(p + 0, v.x);
            atomicAdd(p + 1, v.y);
            atomicAdd(p + 2, v.z);
            atomicAdd(p + 3, v.w);
            if (lane == 0) atomicAdd(&g_counts[s], cnt);
        }
    }
}

// ---------------------------------------------------------------------------
// Pass 3: divide sums by counts in place (L2-hot, ~4.6us measured).
// ---------------------------------------------------------------------------
__global__ void finalize_kernel(float* __restrict__ out) {
    int i = blockIdx.x * blockDim.x + threadIdx.x;
    if (i >= OUT_ELEMS) return;
    int s = i >> 7;  // / D
    int c = g_counts[s];
    if (c < 1) c = 1;
    out[i] = out[i] / (float)c;
}

// ---------------------------------------------------------------------------
// Launch. d_in[0] = inp (float32, n*128), d_in[1] = batch_seg (int32, n).
// Output: (256, 128) float32 means. Three launches, no zero pass, no memsets.
// ---------------------------------------------------------------------------
extern "C" void kernel_launch(void* const* d_in, const int* in_sizes, int n_in,
                              void* d_out, int out_size) {
    const float* inp = (const float*)d_in[0];
    const int* seg = (const int*)d_in[1];
    float* out = (float*)d_out;
    const int n = in_sizes[1];  // number of rows

    segsum_kernel<<<BLOCKS, THREADS>>>((const float4*)inp, seg, out, n);
    merge_kernel<<<BLOCKS, THREADS>>>(out);
    finalize_kernel<<<(OUT_ELEMS + 255) / 256, 256>>>(out);
}